// round 13
// baseline (speedup 1.0000x reference)
#include <cuda_runtime.h>
#include <math.h>

// ---------------- problem constants ----------------
#define D1   4096
#define D2   4096
#define C    16
#define N1   (D2 * C)        // 65536 columns of W1
#define KSPLIT 16
#define KTILE  (D1 / KSPLIT) // 256 rows per split
#define CTILE  128           // threads per gemv block
#define VEC    4             // floats per thread per row-step
#define CPT    (CTILE * VEC) // 512 columns per gemv block
#define NCOLB  (N1 / CPT)    // 128 column-tile blocks
#define ROWS_T (CPT / C)     // 32 DAN rows per column tile
#define PRE    8             // W1 row-steps prefetched before the a0 wait

// ---------------- device scratch (no allocation allowed) ----------------
__device__ float g_a0[D1];                  // layer-0 activations (== a0_copy)
__device__ float g_part[KSPLIT * N1];       // split-K partial sums (4 MB)
__device__ float g_h2p[NCOLB * C];          // per-tile layer-2 partials
__device__ unsigned int g_cnt[NCOLB];       // per-column-tile arrival counters
__device__ unsigned int g_ctr = 0;          // tile-closure counter (self-resets)
__device__ volatile int g_flag[KSPLIT];     // a0-slice-ready flags

// fast tanh: 1 - 2/(exp(2x)+1); __expf/__fdividef handle +-inf saturation.
__device__ __forceinline__ float fast_tanh(float v) {
    return 1.0f - __fdividef(2.0f, __expf(2.0f * v) + 1.0f);
}

// ---------------- shared tiny DAN: 16(+code) -> 15 -> 8 -> 1, tanh ----------------
__device__ __forceinline__ float dan_tanh(
    const float* z, int layer,
    const float* __restrict__ Wd1, const float* __restrict__ bd1,
    const float* __restrict__ Wd2, const float* __restrict__ bd2,
    const float* __restrict__ Wd3, const float* __restrict__ bd3)
{
    // one-hot layer code == row (C+layer) of Wd1 folded in as extra bias
    float h1[15];
#pragma unroll
    for (int j = 0; j < 15; ++j) {
        float v = bd1[j] + Wd1[(C + layer) * 15 + j];
#pragma unroll
        for (int c = 0; c < C; ++c)
            v = fmaf(z[c], Wd1[c * 15 + j], v);
        h1[j] = v > 0.f ? v : 0.01f * v;     // leaky_relu(0.01)
    }
    float h2[8];
#pragma unroll
    for (int j = 0; j < 8; ++j) {
        float v = bd2[j];
#pragma unroll
        for (int i = 0; i < 15; ++i)
            v = fmaf(h1[i], Wd2[i * 8 + j], v);
        h2[j] = v > 0.f ? v : 0.01f * v;
    }
    float o = bd3[0];
#pragma unroll
    for (int i = 0; i < 8; ++i)
        o = fmaf(h2[i], Wd3[i], o);
    return fast_tanh(o);
}

// ---------------- THE kernel: layer0 producers + GEMV + tile closures + final ----------------
// grid = (KSPLIT, NCOLB) = (16, 128). blockIdx.x = K-split (so the 16
// producer blocks, blockIdx.y==0, get the lowest linear ids and run first).
//  * producer (ct==0): computes a0 slice once, publishes, raises g_flag[sp]
//  * consumer: prefetches PRE W1 row-steps, spins on g_flag[sp], streams panel
//  * every block: stores its split partial, bumps g_cnt[ct]; the 16th arriver
//    CLOSES the tile: fixed-order reduce of the 16 partials + bias + skip +
//    DAN1 (32 rows) + layer-2 contribution -> g_h2p[ct]
//  * the last of the 128 tile closers reduces 128x16 + final DAN -> out,
//    and resets g_flag (safe: all blocks passed their spin by then).
// All reductions fixed-order -> deterministic; counters self-reset.
__global__ void __launch_bounds__(CTILE, 4) k_fused(
    const float* __restrict__ x,
    const float* __restrict__ W0, const float* __restrict__ b0,
    const float* __restrict__ W1,
    const float* __restrict__ b1,
    const float* __restrict__ Ws02, const float* __restrict__ bs02,
    const float* __restrict__ W2,   const float* __restrict__ Ws13,
    const float* __restrict__ b2,   const float* __restrict__ bs13,
    const float* __restrict__ Wd1, const float* __restrict__ bd1,
    const float* __restrict__ Wd2, const float* __restrict__ bd2,
    const float* __restrict__ Wd3, const float* __restrict__ bd3,
    float* __restrict__ out)
{
    __shared__ float s[KTILE];
    __shared__ float wp[4 * C];          // per-warp closure partials
    __shared__ bool  shClose, shFinal;
    const int t    = threadIdx.x;
    const int sp   = blockIdx.x;         // K-split index (0..15)
    const int ct   = blockIdx.y;         // column-tile index (0..127)
    const int k0   = sp * KTILE;
    const int col4 = ct * CPT + t * VEC;

    const float4* __restrict__ w =
        reinterpret_cast<const float4*>(W1 + (size_t)k0 * N1 + col4);
    const size_t rowstep = N1 / VEC;

    float4 pre[PRE];
    float4 acc = make_float4(0.f, 0.f, 0.f, 0.f);

    if (ct == 0) {
        // ---- producer: compute a0[k0..k0+256), 2 rows per thread ----
        const float xv = x[0];
#pragma unroll
        for (int i = 0; i < KTILE / CTILE; ++i) {
            const int j = k0 + i * CTILE + t;
            float z[C];
            const float4* w4 = reinterpret_cast<const float4*>(W0 + (size_t)j * C);
            const float4* b4 = reinterpret_cast<const float4*>(b0 + (size_t)j * C);
#pragma unroll
            for (int q = 0; q < 4; ++q) {
                float4 wv = w4[q], bv = b4[q];
                z[4 * q + 0] = fmaf(xv, wv.x, bv.x);
                z[4 * q + 1] = fmaf(xv, wv.y, bv.y);
                z[4 * q + 2] = fmaf(xv, wv.z, bv.z);
                z[4 * q + 3] = fmaf(xv, wv.w, bv.w);
            }
            float a = dan_tanh(z, 0, Wd1, bd1, Wd2, bd2, Wd3, bd3);
            s[i * CTILE + t] = a;
            g_a0[j] = a;
        }
        __threadfence();
        __syncthreads();
        if (t == 0)
            g_flag[sp] = 1;
    } else {
        // ---- consumer: start DRAM pipeline, then wait for the slice ----
#pragma unroll
        for (int i = 0; i < PRE; ++i)
            pre[i] = __ldcs(&w[(size_t)i * rowstep]);
        if (t == 0) {
            while (g_flag[sp] == 0) { }
        }
        __syncthreads();
        __threadfence();
        for (int i = t; i < KTILE; i += CTILE)
            s[i] = g_a0[k0 + i];
        __syncthreads();
#pragma unroll
        for (int i = 0; i < PRE; ++i) {
            float a = s[i];
            acc.x = fmaf(a, pre[i].x, acc.x);
            acc.y = fmaf(a, pre[i].y, acc.y);
            acc.z = fmaf(a, pre[i].z, acc.z);
            acc.w = fmaf(a, pre[i].w, acc.w);
        }
    }

    // ---- main W1 stream ----
    const int kstart = (ct == 0) ? 0 : PRE;
#pragma unroll 8
    for (int kk = kstart; kk < KTILE; ++kk) {
        float4 wv = __ldcs(&w[(size_t)kk * rowstep]);
        float  a  = s[kk];
        acc.x = fmaf(a, wv.x, acc.x);
        acc.y = fmaf(a, wv.y, acc.y);
        acc.z = fmaf(a, wv.z, acc.z);
        acc.w = fmaf(a, wv.w, acc.w);
    }
    *reinterpret_cast<float4*>(&g_part[(size_t)sp * N1 + col4]) = acc;

    // ---- tile arrival: am I the 16th (closing) block for column ct? ----
    __threadfence();
    __syncthreads();
    if (t == 0) {
        unsigned int old = atomicAdd(&g_cnt[ct], 1u);
        shClose = (old == KSPLIT - 1);
        if (shClose) g_cnt[ct] = 0;      // self-reset
    }
    __syncthreads();
    if (!shClose) return;

    // ================= tile closure (one block per ct) =================
    // 32 rows, 4 threads per row; each sub-lane gathers 4 splits.
    {
        const int r   = t >> 2;              // 0..31
        const int sub = t & 3;
        const int j   = ct * ROWS_T + r;     // global DAN row
        float z[C];
#pragma unroll
        for (int c = 0; c < C; ++c) z[c] = 0.f;
#pragma unroll 2
        for (int ii = 0; ii < 4; ++ii) {
            const int ss = sub + ii * 4;
            const float4* p4 =
                reinterpret_cast<const float4*>(&g_part[(size_t)ss * N1 + (size_t)j * C]);
#pragma unroll
            for (int q = 0; q < 4; ++q) {
                float4 p = p4[q];
                z[4 * q + 0] += p.x;
                z[4 * q + 1] += p.y;
                z[4 * q + 2] += p.z;
                z[4 * q + 3] += p.w;
            }
        }
        // quad reduce (fixed order)
#pragma unroll
        for (int c = 0; c < C; ++c) {
            z[c] += __shfl_down_sync(0xffffffffu, z[c], 2);
            z[c] += __shfl_down_sync(0xffffffffu, z[c], 1);
        }

        float v[C];
#pragma unroll
        for (int c = 0; c < C; ++c) v[c] = 0.f;

        if (sub == 0) {
            const float xv = x[0];
            const float4* b4  = reinterpret_cast<const float4*>(b1   + (size_t)j * C);
            const float4* w4  = reinterpret_cast<const float4*>(Ws02 + (size_t)j * C);
            const float4* sb4 = reinterpret_cast<const float4*>(bs02 + (size_t)j * C);
#pragma unroll
            for (int q = 0; q < 4; ++q) {
                float4 b = b4[q], wv = w4[q], sb = sb4[q];
                z[4 * q + 0] += b.x + fmaf(xv, wv.x, sb.x);
                z[4 * q + 1] += b.y + fmaf(xv, wv.y, sb.y);
                z[4 * q + 2] += b.z + fmaf(xv, wv.z, sb.z);
                z[4 * q + 3] += b.w + fmaf(xv, wv.w, sb.w);
            }
            float a1 = dan_tanh(z, 1, Wd1, bd1, Wd2, bd2, Wd3, bd3);
            float a0 = g_a0[j];
            const float4* w2 = reinterpret_cast<const float4*>(W2   + (size_t)j * C);
            const float4* ws = reinterpret_cast<const float4*>(Ws13 + (size_t)j * C);
#pragma unroll
            for (int q = 0; q < 4; ++q) {
                float4 wv = w2[q], sv = ws[q];
                v[4 * q + 0] = fmaf(a1, wv.x, a0 * sv.x);
                v[4 * q + 1] = fmaf(a1, wv.y, a0 * sv.y);
                v[4 * q + 2] = fmaf(a1, wv.z, a0 * sv.z);
                v[4 * q + 3] = fmaf(a1, wv.w, a0 * sv.w);
            }
        }
        // fold the 8 rows of this warp (data at lanes 0,4,...,28)
#pragma unroll
        for (int c = 0; c < C; ++c) {
            v[c] += __shfl_down_sync(0xffffffffu, v[c], 16);
            v[c] += __shfl_down_sync(0xffffffffu, v[c], 8);
            v[c] += __shfl_down_sync(0xffffffffu, v[c], 4);
        }
        if ((t & 31) == 0) {
#pragma unroll
            for (int c = 0; c < C; ++c)
                wp[(t >> 5) * C + c] = v[c];
        }
    }
    __syncthreads();
    if (t < C) {
        float acc2 = 0.f;
#pragma unroll
        for (int wq = 0; wq < 4; ++wq)
            acc2 += wp[wq * C + t];
        g_h2p[ct * C + t] = acc2;
    }

    // ---- final closure: last of the 128 tile closers ----
    __threadfence();
    __syncthreads();
    if (t == 0) {
        unsigned int old = atomicAdd(&g_ctr, 1u);
        shFinal = (old == NCOLB - 1);
        if (shFinal) g_ctr = 0;          // self-reset
    }
    __syncthreads();
    if (!shFinal) return;

    // reset producer flags for the next graph replay (all blocks are past
    // their spin: they had to store partials to let every tile close)
    if (t < KSPLIT)
        g_flag[t] = 0;

    if (t < C) {
        float acc2 = b2[t] + bs13[t];
#pragma unroll 8
        for (int i = 0; i < NCOLB; ++i)
            acc2 += g_h2p[i * C + t];
        wp[t] = acc2;
    }
    __syncthreads();
    if (t == 0) {
        float zf[C];
#pragma unroll
        for (int c = 0; c < C; ++c) zf[c] = wp[c];
        out[0] = dan_tanh(zf, 2, Wd1, bd1, Wd2, bd2, Wd3, bd3);
    }
}

// ---------------- launch ----------------
extern "C" void kernel_launch(void* const* d_in, const int* in_sizes, int n_in,
                              void* d_out, int out_size)
{
    const float* x    = (const float*)d_in[0];
    const float* W0   = (const float*)d_in[1];
    const float* b0   = (const float*)d_in[2];
    const float* W1   = (const float*)d_in[3];
    const float* b1   = (const float*)d_in[4];
    const float* W2   = (const float*)d_in[5];
    const float* b2   = (const float*)d_in[6];
    const float* Ws02 = (const float*)d_in[7];
    const float* bs02 = (const float*)d_in[8];
    const float* Ws13 = (const float*)d_in[9];
    const float* bs13 = (const float*)d_in[10];
    const float* Wd1  = (const float*)d_in[11];
    const float* bd1  = (const float*)d_in[12];
    const float* Wd2  = (const float*)d_in[13];
    const float* bd2  = (const float*)d_in[14];
    const float* Wd3  = (const float*)d_in[15];
    const float* bd3  = (const float*)d_in[16];
    float* out = (float*)d_out;

    dim3 gg(KSPLIT, NCOLB);
    k_fused<<<gg, CTILE>>>(x, W0, b0, W1, b1, Ws02, bs02, W2, Ws13, b2, bs13,
                           Wd1, bd1, Wd2, bd2, Wd3, bd3, out);
}

// round 14
// speedup vs baseline: 1.0168x; 1.0168x over previous
#include <cuda_runtime.h>
#include <math.h>

// ---------------- problem constants ----------------
#define D1   4096
#define D2   4096
#define C    16
#define N1   (D2 * C)        // 65536 columns of W1
#define KSPLIT 16
#define KTILE  (D1 / KSPLIT) // 256 rows per split
#define CTILE  128           // threads per gemv block
#define VEC    4             // floats per thread per row-step
#define CPT    (CTILE * VEC) // 512 columns per gemv block
#define NCOLB  (N1 / CPT)    // 128 column-tile blocks
#define ROWS_T (CPT / C)     // 32 DAN rows per column tile
#define PRE    8             // W1 row-steps prefetched before the a0 wait

// ---------------- device scratch (no allocation allowed) ----------------
__device__ float g_a0[D1];                  // layer-0 activations (== a0_copy)
__device__ float g_part[KSPLIT * N1];       // split-K partial sums (4 MB)
__device__ float g_h2p[NCOLB * C];          // per-tile layer-2 partials
__device__ unsigned int g_cnt[NCOLB];       // per-column-tile arrival counters
__device__ unsigned int g_ctr = 0;          // tile-closure counter (self-resets)
__device__ volatile int g_flag[KSPLIT];     // a0-slice-ready flags

// fast tanh: 1 - 2/(exp(2x)+1); __expf/__fdividef handle +-inf saturation.
__device__ __forceinline__ float fast_tanh(float v) {
    return 1.0f - __fdividef(2.0f, __expf(2.0f * v) + 1.0f);
}

// ---------------- shared tiny DAN: 16(+code) -> 15 -> 8 -> 1, tanh ----------------
__device__ __forceinline__ float dan_tanh(
    const float* z, int layer,
    const float* __restrict__ Wd1, const float* __restrict__ bd1,
    const float* __restrict__ Wd2, const float* __restrict__ bd2,
    const float* __restrict__ Wd3, const float* __restrict__ bd3)
{
    // one-hot layer code == row (C+layer) of Wd1 folded in as extra bias
    float h1[15];
#pragma unroll
    for (int j = 0; j < 15; ++j) {
        float v = bd1[j] + Wd1[(C + layer) * 15 + j];
#pragma unroll
        for (int c = 0; c < C; ++c)
            v = fmaf(z[c], Wd1[c * 15 + j], v);
        h1[j] = v > 0.f ? v : 0.01f * v;     // leaky_relu(0.01)
    }
    float h2[8];
#pragma unroll
    for (int j = 0; j < 8; ++j) {
        float v = bd2[j];
#pragma unroll
        for (int i = 0; i < 15; ++i)
            v = fmaf(h1[i], Wd2[i * 8 + j], v);
        h2[j] = v > 0.f ? v : 0.01f * v;
    }
    float o = bd3[0];
#pragma unroll
    for (int i = 0; i < 8; ++i)
        o = fmaf(h2[i], Wd3[i], o);
    return fast_tanh(o);
}

// ---------------- THE kernel: layer0 producers + GEMV + tile closures + final ----------------
// grid = (KSPLIT, NCOLB) = (16, 128). blockIdx.x = K-split (so the 16
// producer blocks, blockIdx.y==0, get the lowest linear ids and run first).
//  * producer (ct==0): computes a0 slice once, publishes, raises g_flag[sp]
//  * consumer: prefetches PRE W1 row-steps, spins on g_flag[sp], streams panel
//  * every block: stores its split partial, bumps g_cnt[ct]; the 16th arriver
//    CLOSES the tile: fixed-order reduce of the 16 partials + bias + skip +
//    DAN1 (32 rows) + layer-2 contribution -> g_h2p[ct]
//  * the last of the 128 tile closers reduces 128x16 + final DAN -> out,
//    and resets g_flag (safe: all blocks passed their spin by then).
// All reductions fixed-order -> deterministic; counters self-reset.
__global__ void __launch_bounds__(CTILE, 4) k_fused(
    const float* __restrict__ x,
    const float* __restrict__ W0, const float* __restrict__ b0,
    const float* __restrict__ W1,
    const float* __restrict__ b1,
    const float* __restrict__ Ws02, const float* __restrict__ bs02,
    const float* __restrict__ W2,   const float* __restrict__ Ws13,
    const float* __restrict__ b2,   const float* __restrict__ bs13,
    const float* __restrict__ Wd1, const float* __restrict__ bd1,
    const float* __restrict__ Wd2, const float* __restrict__ bd2,
    const float* __restrict__ Wd3, const float* __restrict__ bd3,
    float* __restrict__ out)
{
    __shared__ float s[KTILE];
    __shared__ float wp[4 * C];          // per-warp closure partials
    __shared__ bool  shClose, shFinal;
    const int t    = threadIdx.x;
    const int sp   = blockIdx.x;         // K-split index (0..15)
    const int ct   = blockIdx.y;         // column-tile index (0..127)
    const int k0   = sp * KTILE;
    const int col4 = ct * CPT + t * VEC;

    const float4* __restrict__ w =
        reinterpret_cast<const float4*>(W1 + (size_t)k0 * N1 + col4);
    const size_t rowstep = N1 / VEC;

    float4 pre[PRE];
    float4 acc = make_float4(0.f, 0.f, 0.f, 0.f);

    if (ct == 0) {
        // ---- producer: compute a0[k0..k0+256), 2 rows per thread ----
        const float xv = x[0];
#pragma unroll
        for (int i = 0; i < KTILE / CTILE; ++i) {
            const int j = k0 + i * CTILE + t;
            float z[C];
            const float4* w4 = reinterpret_cast<const float4*>(W0 + (size_t)j * C);
            const float4* b4 = reinterpret_cast<const float4*>(b0 + (size_t)j * C);
#pragma unroll
            for (int q = 0; q < 4; ++q) {
                float4 wv = w4[q], bv = b4[q];
                z[4 * q + 0] = fmaf(xv, wv.x, bv.x);
                z[4 * q + 1] = fmaf(xv, wv.y, bv.y);
                z[4 * q + 2] = fmaf(xv, wv.z, bv.z);
                z[4 * q + 3] = fmaf(xv, wv.w, bv.w);
            }
            float a = dan_tanh(z, 0, Wd1, bd1, Wd2, bd2, Wd3, bd3);
            s[i * CTILE + t] = a;
            g_a0[j] = a;
        }
        __threadfence();
        __syncthreads();
        if (t == 0)
            g_flag[sp] = 1;
    } else {
        // ---- consumer: start DRAM pipeline, then wait for the slice ----
#pragma unroll
        for (int i = 0; i < PRE; ++i)
            pre[i] = __ldcs(&w[(size_t)i * rowstep]);
        if (t == 0) {
            while (g_flag[sp] == 0) { }
        }
        __syncthreads();
        __threadfence();
        for (int i = t; i < KTILE; i += CTILE)
            s[i] = g_a0[k0 + i];
        __syncthreads();
#pragma unroll
        for (int i = 0; i < PRE; ++i) {
            float a = s[i];
            acc.x = fmaf(a, pre[i].x, acc.x);
            acc.y = fmaf(a, pre[i].y, acc.y);
            acc.z = fmaf(a, pre[i].z, acc.z);
            acc.w = fmaf(a, pre[i].w, acc.w);
        }
    }

    // ---- main W1 stream ----
    const int kstart = (ct == 0) ? 0 : PRE;
#pragma unroll 8
    for (int kk = kstart; kk < KTILE; ++kk) {
        float4 wv = __ldcs(&w[(size_t)kk * rowstep]);
        float  a  = s[kk];
        acc.x = fmaf(a, wv.x, acc.x);
        acc.y = fmaf(a, wv.y, acc.y);
        acc.z = fmaf(a, wv.z, acc.z);
        acc.w = fmaf(a, wv.w, acc.w);
    }
    *reinterpret_cast<float4*>(&g_part[(size_t)sp * N1 + col4]) = acc;

    // ---- tile arrival: am I the 16th (closing) block for column ct? ----
    __threadfence();
    __syncthreads();
    if (t == 0) {
        unsigned int old = atomicAdd(&g_cnt[ct], 1u);
        shClose = (old == KSPLIT - 1);
        if (shClose) g_cnt[ct] = 0;      // self-reset
    }
    __syncthreads();
    if (!shClose) return;

    // ================= tile closure (one block per ct) =================
    // 32 rows, 4 threads per row; each sub-lane gathers 4 splits.
    {
        const int r   = t >> 2;              // 0..31
        const int sub = t & 3;
        const int j   = ct * ROWS_T + r;     // global DAN row
        float z[C];
#pragma unroll
        for (int c = 0; c < C; ++c) z[c] = 0.f;
#pragma unroll 2
        for (int ii = 0; ii < 4; ++ii) {
            const int ss = sub + ii * 4;
            const float4* p4 =
                reinterpret_cast<const float4*>(&g_part[(size_t)ss * N1 + (size_t)j * C]);
#pragma unroll
            for (int q = 0; q < 4; ++q) {
                float4 p = p4[q];
                z[4 * q + 0] += p.x;
                z[4 * q + 1] += p.y;
                z[4 * q + 2] += p.z;
                z[4 * q + 3] += p.w;
            }
        }
        // quad reduce (fixed order)
#pragma unroll
        for (int c = 0; c < C; ++c) {
            z[c] += __shfl_down_sync(0xffffffffu, z[c], 2);
            z[c] += __shfl_down_sync(0xffffffffu, z[c], 1);
        }

        float v[C];
#pragma unroll
        for (int c = 0; c < C; ++c) v[c] = 0.f;

        if (sub == 0) {
            const float xv = x[0];
            const float4* b4  = reinterpret_cast<const float4*>(b1   + (size_t)j * C);
            const float4* w4  = reinterpret_cast<const float4*>(Ws02 + (size_t)j * C);
            const float4* sb4 = reinterpret_cast<const float4*>(bs02 + (size_t)j * C);
#pragma unroll
            for (int q = 0; q < 4; ++q) {
                float4 b = b4[q], wv = w4[q], sb = sb4[q];
                z[4 * q + 0] += b.x + fmaf(xv, wv.x, sb.x);
                z[4 * q + 1] += b.y + fmaf(xv, wv.y, sb.y);
                z[4 * q + 2] += b.z + fmaf(xv, wv.z, sb.z);
                z[4 * q + 3] += b.w + fmaf(xv, wv.w, sb.w);
            }
            float a1 = dan_tanh(z, 1, Wd1, bd1, Wd2, bd2, Wd3, bd3);
            float a0 = g_a0[j];
            const float4* w2 = reinterpret_cast<const float4*>(W2   + (size_t)j * C);
            const float4* ws = reinterpret_cast<const float4*>(Ws13 + (size_t)j * C);
#pragma unroll
            for (int q = 0; q < 4; ++q) {
                float4 wv = w2[q], sv = ws[q];
                v[4 * q + 0] = fmaf(a1, wv.x, a0 * sv.x);
                v[4 * q + 1] = fmaf(a1, wv.y, a0 * sv.y);
                v[4 * q + 2] = fmaf(a1, wv.z, a0 * sv.z);
                v[4 * q + 3] = fmaf(a1, wv.w, a0 * sv.w);
            }
        }
        // fold the 8 rows of this warp (data at lanes 0,4,...,28)
#pragma unroll
        for (int c = 0; c < C; ++c) {
            v[c] += __shfl_down_sync(0xffffffffu, v[c], 16);
            v[c] += __shfl_down_sync(0xffffffffu, v[c], 8);
            v[c] += __shfl_down_sync(0xffffffffu, v[c], 4);
        }
        if ((t & 31) == 0) {
#pragma unroll
            for (int c = 0; c < C; ++c)
                wp[(t >> 5) * C + c] = v[c];
        }
    }
    __syncthreads();
    if (t < C) {
        float acc2 = 0.f;
#pragma unroll
        for (int wq = 0; wq < 4; ++wq)
            acc2 += wp[wq * C + t];
        g_h2p[ct * C + t] = acc2;
    }

    // ---- final closure: last of the 128 tile closers ----
    __threadfence();
    __syncthreads();
    if (t == 0) {
        unsigned int old = atomicAdd(&g_ctr, 1u);
        shFinal = (old == NCOLB - 1);
        if (shFinal) g_ctr = 0;          // self-reset
    }
    __syncthreads();
    if (!shFinal) return;

    // reset producer flags for the next graph replay (all blocks are past
    // their spin: they had to store partials to let every tile close)
    if (t < KSPLIT)
        g_flag[t] = 0;

    if (t < C) {
        float acc2 = b2[t] + bs13[t];
#pragma unroll 8
        for (int i = 0; i < NCOLB; ++i)
            acc2 += g_h2p[i * C + t];
        wp[t] = acc2;
    }
    __syncthreads();
    if (t == 0) {
        float zf[C];
#pragma unroll
        for (int c = 0; c < C; ++c) zf[c] = wp[c];
        out[0] = dan_tanh(zf, 2, Wd1, bd1, Wd2, bd2, Wd3, bd3);
    }
}

// ---------------- launch ----------------
extern "C" void kernel_launch(void* const* d_in, const int* in_sizes, int n_in,
                              void* d_out, int out_size)
{
    const float* x    = (const float*)d_in[0];
    const float* W0   = (const float*)d_in[1];
    const float* b0   = (const float*)d_in[2];
    const float* W1   = (const float*)d_in[3];
    const float* b1   = (const float*)d_in[4];
    const float* W2   = (const float*)d_in[5];
    const float* b2   = (const float*)d_in[6];
    const float* Ws02 = (const float*)d_in[7];
    const float* bs02 = (const float*)d_in[8];
    const float* Ws13 = (const float*)d_in[9];
    const float* bs13 = (const float*)d_in[10];
    const float* Wd1  = (const float*)d_in[11];
    const float* bd1  = (const float*)d_in[12];
    const float* Wd2  = (const float*)d_in[13];
    const float* bd2  = (const float*)d_in[14];
    const float* Wd3  = (const float*)d_in[15];
    const float* bd3  = (const float*)d_in[16];
    float* out = (float*)d_out;

    dim3 gg(KSPLIT, NCOLB);
    k_fused<<<gg, CTILE>>>(x, W0, b0, W1, b1, Ws02, bs02, W2, Ws13, b2, bs13,
                           Wd1, bd1, Wd2, bd2, Wd3, bd3, out);
}

// round 15
// speedup vs baseline: 1.0181x; 1.0013x over previous
#include <cuda_runtime.h>
#include <math.h>

// ---------------- problem constants ----------------
#define D1   4096
#define D2   4096
#define C    16
#define N1   (D2 * C)        // 65536 columns of W1
#define KSPLIT 16
#define KTILE  (D1 / KSPLIT) // 256 rows per split
#define CTILE  128           // threads per gemv block
#define VEC    4             // floats per thread per row-step
#define CPT    (CTILE * VEC) // 512 columns per gemv block
#define NCOLB  (N1 / CPT)    // 128 column-tile blocks
#define ROWS_T (CPT / C)     // 32 DAN rows per column tile
#define PRE    8             // W1 row-steps prefetched before the a0 wait

// ---------------- device scratch (no allocation allowed) ----------------
__device__ float g_a0[D1];                  // layer-0 activations (== a0_copy)
__device__ float g_part[KSPLIT * N1];       // split-K partial sums (4 MB)
__device__ float g_h2p[NCOLB * C];          // per-tile layer-2 partials
__device__ unsigned int g_cnt[NCOLB];       // per-column-tile arrival counters
__device__ unsigned int g_ctr = 0;          // tile-closure counter (self-resets)
__device__ volatile int g_flag[KSPLIT];     // a0-slice-ready flags

// fast tanh: 1 - 2/(exp(2x)+1); __expf/__fdividef handle +-inf saturation.
__device__ __forceinline__ float fast_tanh(float v) {
    return 1.0f - __fdividef(2.0f, __expf(2.0f * v) + 1.0f);
}

// ---------------- shared tiny DAN: 16(+code) -> 15 -> 8 -> 1, tanh ----------------
__device__ __forceinline__ float dan_tanh(
    const float* z, int layer,
    const float* __restrict__ Wd1, const float* __restrict__ bd1,
    const float* __restrict__ Wd2, const float* __restrict__ bd2,
    const float* __restrict__ Wd3, const float* __restrict__ bd3)
{
    // one-hot layer code == row (C+layer) of Wd1 folded in as extra bias
    float h1[15];
#pragma unroll
    for (int j = 0; j < 15; ++j) {
        float v = bd1[j] + Wd1[(C + layer) * 15 + j];
#pragma unroll
        for (int c = 0; c < C; ++c)
            v = fmaf(z[c], Wd1[c * 15 + j], v);
        h1[j] = v > 0.f ? v : 0.01f * v;     // leaky_relu(0.01)
    }
    float h2[8];
#pragma unroll
    for (int j = 0; j < 8; ++j) {
        float v = bd2[j];
#pragma unroll
        for (int i = 0; i < 15; ++i)
            v = fmaf(h1[i], Wd2[i * 8 + j], v);
        h2[j] = v > 0.f ? v : 0.01f * v;
    }
    float o = bd3[0];
#pragma unroll
    for (int i = 0; i < 8; ++i)
        o = fmaf(h2[i], Wd3[i], o);
    return fast_tanh(o);
}

// ---------------- THE kernel: layer0 producers + GEMV + tile closures + final ----------------
// grid = (KSPLIT, NCOLB) = (16, 128). blockIdx.x = K-split (so the 16
// producer blocks, blockIdx.y==0, get the lowest linear ids and run first).
//  * producer (ct==0): computes a0 slice once, publishes, raises g_flag[sp]
//  * consumer: prefetches PRE W1 row-steps, spins on g_flag[sp], streams panel
//  * every block: stores its split partial, bumps g_cnt[ct]; the 16th arriver
//    CLOSES the tile: fixed-order reduce of the 16 partials + bias + skip +
//    DAN1 (32 rows) + layer-2 contribution -> g_h2p[ct]
//  * the last of the 128 tile closers reduces 128x16 + final DAN -> out,
//    and resets g_flag (safe: all blocks passed their spin by then).
// All reductions fixed-order -> deterministic; counters self-reset.
__global__ void __launch_bounds__(CTILE, 4) k_fused(
    const float* __restrict__ x,
    const float* __restrict__ W0, const float* __restrict__ b0,
    const float* __restrict__ W1,
    const float* __restrict__ b1,
    const float* __restrict__ Ws02, const float* __restrict__ bs02,
    const float* __restrict__ W2,   const float* __restrict__ Ws13,
    const float* __restrict__ b2,   const float* __restrict__ bs13,
    const float* __restrict__ Wd1, const float* __restrict__ bd1,
    const float* __restrict__ Wd2, const float* __restrict__ bd2,
    const float* __restrict__ Wd3, const float* __restrict__ bd3,
    float* __restrict__ out)
{
    __shared__ float s[KTILE];
    __shared__ float wp[4 * C];          // per-warp closure partials
    __shared__ bool  shClose, shFinal;
    const int t    = threadIdx.x;
    const int sp   = blockIdx.x;         // K-split index (0..15)
    const int ct   = blockIdx.y;         // column-tile index (0..127)
    const int k0   = sp * KTILE;
    const int col4 = ct * CPT + t * VEC;

    const float4* __restrict__ w =
        reinterpret_cast<const float4*>(W1 + (size_t)k0 * N1 + col4);
    const size_t rowstep = N1 / VEC;

    float4 pre[PRE];
    float4 acc = make_float4(0.f, 0.f, 0.f, 0.f);

    if (ct == 0) {
        // ---- producer: compute a0[k0..k0+256), 2 rows per thread ----
        const float xv = x[0];
#pragma unroll
        for (int i = 0; i < KTILE / CTILE; ++i) {
            const int j = k0 + i * CTILE + t;
            float z[C];
            const float4* w4 = reinterpret_cast<const float4*>(W0 + (size_t)j * C);
            const float4* b4 = reinterpret_cast<const float4*>(b0 + (size_t)j * C);
#pragma unroll
            for (int q = 0; q < 4; ++q) {
                float4 wv = w4[q], bv = b4[q];
                z[4 * q + 0] = fmaf(xv, wv.x, bv.x);
                z[4 * q + 1] = fmaf(xv, wv.y, bv.y);
                z[4 * q + 2] = fmaf(xv, wv.z, bv.z);
                z[4 * q + 3] = fmaf(xv, wv.w, bv.w);
            }
            float a = dan_tanh(z, 0, Wd1, bd1, Wd2, bd2, Wd3, bd3);
            s[i * CTILE + t] = a;
            g_a0[j] = a;
        }
        __threadfence();
        __syncthreads();
        if (t == 0)
            g_flag[sp] = 1;
    } else {
        // ---- consumer: start DRAM pipeline, then wait for the slice ----
#pragma unroll
        for (int i = 0; i < PRE; ++i)
            pre[i] = __ldcs(&w[(size_t)i * rowstep]);
        if (t == 0) {
            while (g_flag[sp] == 0) { }
        }
        __syncthreads();
        __threadfence();
        for (int i = t; i < KTILE; i += CTILE)
            s[i] = g_a0[k0 + i];
        __syncthreads();
#pragma unroll
        for (int i = 0; i < PRE; ++i) {
            float a = s[i];
            acc.x = fmaf(a, pre[i].x, acc.x);
            acc.y = fmaf(a, pre[i].y, acc.y);
            acc.z = fmaf(a, pre[i].z, acc.z);
            acc.w = fmaf(a, pre[i].w, acc.w);
        }
    }

    // ---- main W1 stream ----
    const int kstart = (ct == 0) ? 0 : PRE;
#pragma unroll 8
    for (int kk = kstart; kk < KTILE; ++kk) {
        float4 wv = __ldcs(&w[(size_t)kk * rowstep]);
        float  a  = s[kk];
        acc.x = fmaf(a, wv.x, acc.x);
        acc.y = fmaf(a, wv.y, acc.y);
        acc.z = fmaf(a, wv.z, acc.z);
        acc.w = fmaf(a, wv.w, acc.w);
    }
    *reinterpret_cast<float4*>(&g_part[(size_t)sp * N1 + col4]) = acc;

    // ---- tile arrival: am I the 16th (closing) block for column ct? ----
    __threadfence();
    __syncthreads();
    if (t == 0) {
        unsigned int old = atomicAdd(&g_cnt[ct], 1u);
        shClose = (old == KSPLIT - 1);
        if (shClose) g_cnt[ct] = 0;      // self-reset
    }
    __syncthreads();
    if (!shClose) return;

    // ================= tile closure (one block per ct) =================
    // 32 rows, 4 threads per row; each sub-lane gathers 4 splits.
    {
        const int r   = t >> 2;              // 0..31
        const int sub = t & 3;
        const int j   = ct * ROWS_T + r;     // global DAN row
        float z[C];
#pragma unroll
        for (int c = 0; c < C; ++c) z[c] = 0.f;
#pragma unroll 2
        for (int ii = 0; ii < 4; ++ii) {
            const int ss = sub + ii * 4;
            const float4* p4 =
                reinterpret_cast<const float4*>(&g_part[(size_t)ss * N1 + (size_t)j * C]);
#pragma unroll
            for (int q = 0; q < 4; ++q) {
                float4 p = p4[q];
                z[4 * q + 0] += p.x;
                z[4 * q + 1] += p.y;
                z[4 * q + 2] += p.z;
                z[4 * q + 3] += p.w;
            }
        }
        // quad reduce (fixed order)
#pragma unroll
        for (int c = 0; c < C; ++c) {
            z[c] += __shfl_down_sync(0xffffffffu, z[c], 2);
            z[c] += __shfl_down_sync(0xffffffffu, z[c], 1);
        }

        float v[C];
#pragma unroll
        for (int c = 0; c < C; ++c) v[c] = 0.f;

        if (sub == 0) {
            const float xv = x[0];
            const float4* b4  = reinterpret_cast<const float4*>(b1   + (size_t)j * C);
            const float4* w4  = reinterpret_cast<const float4*>(Ws02 + (size_t)j * C);
            const float4* sb4 = reinterpret_cast<const float4*>(bs02 + (size_t)j * C);
#pragma unroll
            for (int q = 0; q < 4; ++q) {
                float4 b = b4[q], wv = w4[q], sb = sb4[q];
                z[4 * q + 0] += b.x + fmaf(xv, wv.x, sb.x);
                z[4 * q + 1] += b.y + fmaf(xv, wv.y, sb.y);
                z[4 * q + 2] += b.z + fmaf(xv, wv.z, sb.z);
                z[4 * q + 3] += b.w + fmaf(xv, wv.w, sb.w);
            }
            float a1 = dan_tanh(z, 1, Wd1, bd1, Wd2, bd2, Wd3, bd3);
            float a0 = g_a0[j];
            const float4* w2 = reinterpret_cast<const float4*>(W2   + (size_t)j * C);
            const float4* ws = reinterpret_cast<const float4*>(Ws13 + (size_t)j * C);
#pragma unroll
            for (int q = 0; q < 4; ++q) {
                float4 wv = w2[q], sv = ws[q];
                v[4 * q + 0] = fmaf(a1, wv.x, a0 * sv.x);
                v[4 * q + 1] = fmaf(a1, wv.y, a0 * sv.y);
                v[4 * q + 2] = fmaf(a1, wv.z, a0 * sv.z);
                v[4 * q + 3] = fmaf(a1, wv.w, a0 * sv.w);
            }
        }
        // fold the 8 rows of this warp (data at lanes 0,4,...,28)
#pragma unroll
        for (int c = 0; c < C; ++c) {
            v[c] += __shfl_down_sync(0xffffffffu, v[c], 16);
            v[c] += __shfl_down_sync(0xffffffffu, v[c], 8);
            v[c] += __shfl_down_sync(0xffffffffu, v[c], 4);
        }
        if ((t & 31) == 0) {
#pragma unroll
            for (int c = 0; c < C; ++c)
                wp[(t >> 5) * C + c] = v[c];
        }
    }
    __syncthreads();
    if (t < C) {
        float acc2 = 0.f;
#pragma unroll
        for (int wq = 0; wq < 4; ++wq)
            acc2 += wp[wq * C + t];
        g_h2p[ct * C + t] = acc2;
    }

    // ---- final closure: last of the 128 tile closers ----
    __threadfence();
    __syncthreads();
    if (t == 0) {
        unsigned int old = atomicAdd(&g_ctr, 1u);
        shFinal = (old == NCOLB - 1);
        if (shFinal) g_ctr = 0;          // self-reset
    }
    __syncthreads();
    if (!shFinal) return;

    // reset producer flags for the next graph replay (all blocks are past
    // their spin: they had to store partials to let every tile close)
    if (t < KSPLIT)
        g_flag[t] = 0;

    if (t < C) {
        float acc2 = b2[t] + bs13[t];
#pragma unroll 8
        for (int i = 0; i < NCOLB; ++i)
            acc2 += g_h2p[i * C + t];
        wp[t] = acc2;
    }
    __syncthreads();
    if (t == 0) {
        float zf[C];
#pragma unroll
        for (int c = 0; c < C; ++c) zf[c] = wp[c];
        out[0] = dan_tanh(zf, 2, Wd1, bd1, Wd2, bd2, Wd3, bd3);
    }
}

// ---------------- launch ----------------
extern "C" void kernel_launch(void* const* d_in, const int* in_sizes, int n_in,
                              void* d_out, int out_size)
{
    const float* x    = (const float*)d_in[0];
    const float* W0   = (const float*)d_in[1];
    const float* b0   = (const float*)d_in[2];
    const float* W1   = (const float*)d_in[3];
    const float* b1   = (const float*)d_in[4];
    const float* W2   = (const float*)d_in[5];
    const float* b2   = (const float*)d_in[6];
    const float* Ws02 = (const float*)d_in[7];
    const float* bs02 = (const float*)d_in[8];
    const float* Ws13 = (const float*)d_in[9];
    const float* bs13 = (const float*)d_in[10];
    const float* Wd1  = (const float*)d_in[11];
    const float* bd1  = (const float*)d_in[12];
    const float* Wd2  = (const float*)d_in[13];
    const float* bd2  = (const float*)d_in[14];
    const float* Wd3  = (const float*)d_in[15];
    const float* bd3  = (const float*)d_in[16];
    float* out = (float*)d_out;

    dim3 gg(KSPLIT, NCOLB);
    k_fused<<<gg, CTILE>>>(x, W0, b0, W1, b1, Ws02, bs02, W2, Ws13, b2, bs13,
                           Wd1, bd1, Wd2, bd2, Wd3, bd3, out);
}

// round 16
// speedup vs baseline: 1.0287x; 1.0104x over previous
#include <cuda_runtime.h>
#include <math.h>

// ---------------- problem constants ----------------
#define D1   4096
#define D2   4096
#define C    16
#define N1   (D2 * C)        // 65536 columns of W1
#define KSPLIT 16
#define KTILE  (D1 / KSPLIT) // 256 rows per split
#define CTILE  128           // threads per gemv block
#define VEC    4             // floats per thread per row-step
#define CPT    (CTILE * VEC) // 512 columns per gemv block
#define NCOLB  (N1 / CPT)    // 128 column-tile blocks
#define ROWS_T (CPT / C)     // 32 DAN rows per column tile
#define PRE    8             // W1 row-steps prefetched before the a0 wait

// ---------------- device scratch (no allocation allowed) ----------------
__device__ float g_a0[D1];                  // layer-0 activations (== a0_copy)
__device__ float g_part[KSPLIT * N1];       // split-K partial sums (4 MB)
__device__ float g_h2p[NCOLB * C];          // per-tile layer-2 partials
__device__ unsigned int g_cnt[NCOLB];       // per-column-tile arrival counters
__device__ unsigned int g_ctr = 0;          // tile-closure counter (self-resets)
__device__ volatile int g_flag[KSPLIT];     // a0-slice-ready flags

// fast tanh: 1 - 2/(exp(2x)+1); __expf/__fdividef handle +-inf saturation.
__device__ __forceinline__ float fast_tanh(float v) {
    return 1.0f - __fdividef(2.0f, __expf(2.0f * v) + 1.0f);
}

// ---------------- shared tiny DAN: 16(+code) -> 15 -> 8 -> 1, tanh ----------------
__device__ __forceinline__ float dan_tanh(
    const float* z, int layer,
    const float* __restrict__ Wd1, const float* __restrict__ bd1,
    const float* __restrict__ Wd2, const float* __restrict__ bd2,
    const float* __restrict__ Wd3, const float* __restrict__ bd3)
{
    // one-hot layer code == row (C+layer) of Wd1 folded in as extra bias
    float h1[15];
#pragma unroll
    for (int j = 0; j < 15; ++j) {
        float v = bd1[j] + Wd1[(C + layer) * 15 + j];
#pragma unroll
        for (int c = 0; c < C; ++c)
            v = fmaf(z[c], Wd1[c * 15 + j], v);
        h1[j] = v > 0.f ? v : 0.01f * v;     // leaky_relu(0.01)
    }
    float h2[8];
#pragma unroll
    for (int j = 0; j < 8; ++j) {
        float v = bd2[j];
#pragma unroll
        for (int i = 0; i < 15; ++i)
            v = fmaf(h1[i], Wd2[i * 8 + j], v);
        h2[j] = v > 0.f ? v : 0.01f * v;
    }
    float o = bd3[0];
#pragma unroll
    for (int i = 0; i < 8; ++i)
        o = fmaf(h2[i], Wd3[i], o);
    return fast_tanh(o);
}

// ---------------- THE kernel: layer0 producers + GEMV + tile closures + final ----------------
// grid = (KSPLIT, NCOLB) = (16, 128). blockIdx.x = K-split (so the 16
// producer blocks, blockIdx.y==0, get the lowest linear ids and run first).
//  * producer (ct==0): computes a0 slice once, publishes, raises g_flag[sp]
//  * consumer: prefetches PRE W1 row-steps, spins on g_flag[sp], streams panel
//  * every block: stores its split partial, bumps g_cnt[ct]; the 16th arriver
//    CLOSES the tile: fixed-order reduce of the 16 partials + bias + skip +
//    DAN1 (32 rows) + layer-2 contribution -> g_h2p[ct]
//  * the last of the 128 tile closers reduces 128x16 + final DAN -> out,
//    and resets g_flag (safe: all blocks passed their spin by then).
// All reductions fixed-order -> deterministic; counters self-reset.
// __launch_bounds__(128, 8): cap regs at 64 so 8 blocks/SM are resident
// (32 warps, ~47% occ) -- the hot stream loop fits in 64 regs; any spills
// land in the rare producer/closure paths, off the bandwidth-critical path.
__global__ void __launch_bounds__(CTILE, 8) k_fused(
    const float* __restrict__ x,
    const float* __restrict__ W0, const float* __restrict__ b0,
    const float* __restrict__ W1,
    const float* __restrict__ b1,
    const float* __restrict__ Ws02, const float* __restrict__ bs02,
    const float* __restrict__ W2,   const float* __restrict__ Ws13,
    const float* __restrict__ b2,   const float* __restrict__ bs13,
    const float* __restrict__ Wd1, const float* __restrict__ bd1,
    const float* __restrict__ Wd2, const float* __restrict__ bd2,
    const float* __restrict__ Wd3, const float* __restrict__ bd3,
    float* __restrict__ out)
{
    __shared__ float s[KTILE];
    __shared__ float wp[4 * C];          // per-warp closure partials
    __shared__ bool  shClose, shFinal;
    const int t    = threadIdx.x;
    const int sp   = blockIdx.x;         // K-split index (0..15)
    const int ct   = blockIdx.y;         // column-tile index (0..127)
    const int k0   = sp * KTILE;
    const int col4 = ct * CPT + t * VEC;

    const float4* __restrict__ w =
        reinterpret_cast<const float4*>(W1 + (size_t)k0 * N1 + col4);
    const size_t rowstep = N1 / VEC;

    float4 pre[PRE];
    float4 acc = make_float4(0.f, 0.f, 0.f, 0.f);

    if (ct == 0) {
        // ---- producer: compute a0[k0..k0+256), 2 rows per thread ----
        const float xv = x[0];
#pragma unroll
        for (int i = 0; i < KTILE / CTILE; ++i) {
            const int j = k0 + i * CTILE + t;
            float z[C];
            const float4* w4 = reinterpret_cast<const float4*>(W0 + (size_t)j * C);
            const float4* b4 = reinterpret_cast<const float4*>(b0 + (size_t)j * C);
#pragma unroll
            for (int q = 0; q < 4; ++q) {
                float4 wv = w4[q], bv = b4[q];
                z[4 * q + 0] = fmaf(xv, wv.x, bv.x);
                z[4 * q + 1] = fmaf(xv, wv.y, bv.y);
                z[4 * q + 2] = fmaf(xv, wv.z, bv.z);
                z[4 * q + 3] = fmaf(xv, wv.w, bv.w);
            }
            float a = dan_tanh(z, 0, Wd1, bd1, Wd2, bd2, Wd3, bd3);
            s[i * CTILE + t] = a;
            g_a0[j] = a;
        }
        __threadfence();
        __syncthreads();
        if (t == 0)
            g_flag[sp] = 1;
    } else {
        // ---- consumer: start DRAM pipeline, then wait for the slice ----
#pragma unroll
        for (int i = 0; i < PRE; ++i)
            pre[i] = __ldcs(&w[(size_t)i * rowstep]);
        if (t == 0) {
            while (g_flag[sp] == 0) { }
        }
        __syncthreads();
        __threadfence();
        for (int i = t; i < KTILE; i += CTILE)
            s[i] = g_a0[k0 + i];
        __syncthreads();
#pragma unroll
        for (int i = 0; i < PRE; ++i) {
            float a = s[i];
            acc.x = fmaf(a, pre[i].x, acc.x);
            acc.y = fmaf(a, pre[i].y, acc.y);
            acc.z = fmaf(a, pre[i].z, acc.z);
            acc.w = fmaf(a, pre[i].w, acc.w);
        }
    }

    // ---- main W1 stream ----
    const int kstart = (ct == 0) ? 0 : PRE;
#pragma unroll 8
    for (int kk = kstart; kk < KTILE; ++kk) {
        float4 wv = __ldcs(&w[(size_t)kk * rowstep]);
        float  a  = s[kk];
        acc.x = fmaf(a, wv.x, acc.x);
        acc.y = fmaf(a, wv.y, acc.y);
        acc.z = fmaf(a, wv.z, acc.z);
        acc.w = fmaf(a, wv.w, acc.w);
    }
    *reinterpret_cast<float4*>(&g_part[(size_t)sp * N1 + col4]) = acc;

    // ---- tile arrival: am I the 16th (closing) block for column ct? ----
    __threadfence();
    __syncthreads();
    if (t == 0) {
        unsigned int old = atomicAdd(&g_cnt[ct], 1u);
        shClose = (old == KSPLIT - 1);
        if (shClose) g_cnt[ct] = 0;      // self-reset
    }
    __syncthreads();
    if (!shClose) return;

    // ================= tile closure (one block per ct) =================
    // 32 rows, 4 threads per row; each sub-lane gathers 4 splits.
    {
        const int r   = t >> 2;              // 0..31
        const int sub = t & 3;
        const int j   = ct * ROWS_T + r;     // global DAN row
        float z[C];
#pragma unroll
        for (int c = 0; c < C; ++c) z[c] = 0.f;
#pragma unroll 2
        for (int ii = 0; ii < 4; ++ii) {
            const int ss = sub + ii * 4;
            const float4* p4 =
                reinterpret_cast<const float4*>(&g_part[(size_t)ss * N1 + (size_t)j * C]);
#pragma unroll
            for (int q = 0; q < 4; ++q) {
                float4 p = p4[q];
                z[4 * q + 0] += p.x;
                z[4 * q + 1] += p.y;
                z[4 * q + 2] += p.z;
                z[4 * q + 3] += p.w;
            }
        }
        // quad reduce (fixed order)
#pragma unroll
        for (int c = 0; c < C; ++c) {
            z[c] += __shfl_down_sync(0xffffffffu, z[c], 2);
            z[c] += __shfl_down_sync(0xffffffffu, z[c], 1);
        }

        float v[C];
#pragma unroll
        for (int c = 0; c < C; ++c) v[c] = 0.f;

        if (sub == 0) {
            const float xv = x[0];
            const float4* b4  = reinterpret_cast<const float4*>(b1   + (size_t)j * C);
            const float4* w4  = reinterpret_cast<const float4*>(Ws02 + (size_t)j * C);
            const float4* sb4 = reinterpret_cast<const float4*>(bs02 + (size_t)j * C);
#pragma unroll
            for (int q = 0; q < 4; ++q) {
                float4 b = b4[q], wv = w4[q], sb = sb4[q];
                z[4 * q + 0] += b.x + fmaf(xv, wv.x, sb.x);
                z[4 * q + 1] += b.y + fmaf(xv, wv.y, sb.y);
                z[4 * q + 2] += b.z + fmaf(xv, wv.z, sb.z);
                z[4 * q + 3] += b.w + fmaf(xv, wv.w, sb.w);
            }
            float a1 = dan_tanh(z, 1, Wd1, bd1, Wd2, bd2, Wd3, bd3);
            float a0 = g_a0[j];
            const float4* w2 = reinterpret_cast<const float4*>(W2   + (size_t)j * C);
            const float4* ws = reinterpret_cast<const float4*>(Ws13 + (size_t)j * C);
#pragma unroll
            for (int q = 0; q < 4; ++q) {
                float4 wv = w2[q], sv = ws[q];
                v[4 * q + 0] = fmaf(a1, wv.x, a0 * sv.x);
                v[4 * q + 1] = fmaf(a1, wv.y, a0 * sv.y);
                v[4 * q + 2] = fmaf(a1, wv.z, a0 * sv.z);
                v[4 * q + 3] = fmaf(a1, wv.w, a0 * sv.w);
            }
        }
        // fold the 8 rows of this warp (data at lanes 0,4,...,28)
#pragma unroll
        for (int c = 0; c < C; ++c) {
            v[c] += __shfl_down_sync(0xffffffffu, v[c], 16);
            v[c] += __shfl_down_sync(0xffffffffu, v[c], 8);
            v[c] += __shfl_down_sync(0xffffffffu, v[c], 4);
        }
        if ((t & 31) == 0) {
#pragma unroll
            for (int c = 0; c < C; ++c)
                wp[(t >> 5) * C + c] = v[c];
        }
    }
    __syncthreads();
    if (t < C) {
        float acc2 = 0.f;
#pragma unroll
        for (int wq = 0; wq < 4; ++wq)
            acc2 += wp[wq * C + t];
        g_h2p[ct * C + t] = acc2;
    }

    // ---- final closure: last of the 128 tile closers ----
    __threadfence();
    __syncthreads();
    if (t == 0) {
        unsigned int old = atomicAdd(&g_ctr, 1u);
        shFinal = (old == NCOLB - 1);
        if (shFinal) g_ctr = 0;          // self-reset
    }
    __syncthreads();
    if (!shFinal) return;

    // reset producer flags for the next graph replay (all blocks are past
    // their spin: they had to store partials to let every tile close)
    if (t < KSPLIT)
        g_flag[t] = 0;

    if (t < C) {
        float acc2 = b2[t] + bs13[t];
#pragma unroll 8
        for (int i = 0; i < NCOLB; ++i)
            acc2 += g_h2p[i * C + t];
        wp[t] = acc2;
    }
    __syncthreads();
    if (t == 0) {
        float zf[C];
#pragma unroll
        for (int c = 0; c < C; ++c) zf[c] = wp[c];
        out[0] = dan_tanh(zf, 2, Wd1, bd1, Wd2, bd2, Wd3, bd3);
    }
}

// ---------------- launch ----------------
extern "C" void kernel_launch(void* const* d_in, const int* in_sizes, int n_in,
                              void* d_out, int out_size)
{
    const float* x    = (const float*)d_in[0];
    const float* W0   = (const float*)d_in[1];
    const float* b0   = (const float*)d_in[2];
    const float* W1   = (const float*)d_in[3];
    const float* b1   = (const float*)d_in[4];
    const float* W2   = (const float*)d_in[5];
    const float* b2   = (const float*)d_in[6];
    const float* Ws02 = (const float*)d_in[7];
    const float* bs02 = (const float*)d_in[8];
    const float* Ws13 = (const float*)d_in[9];
    const float* bs13 = (const float*)d_in[10];
    const float* Wd1  = (const float*)d_in[11];
    const float* bd1  = (const float*)d_in[12];
    const float* Wd2  = (const float*)d_in[13];
    const float* bd2  = (const float*)d_in[14];
    const float* Wd3  = (const float*)d_in[15];
    const float* bd3  = (const float*)d_in[16];
    float* out = (float*)d_out;

    dim3 gg(KSPLIT, NCOLB);
    k_fused<<<gg, CTILE>>>(x, W0, b0, W1, b1, Ws02, bs02, W2, Ws13, b2, bs13,
                           Wd1, bd1, Wd2, bd2, Wd3, bd3, out);
}